// round 10
// baseline (speedup 1.0000x reference)
#include <cuda_runtime.h>

#define BB 8
#define SS 32
#define PP 8
#define VV 8000
#define DD 128
#define CONCF 5.0f
#define EPSF 1e-8f

#define NT_ATTN 512
#define NQ (VV/4)        /* 2000 float4 per row */

/* ---- gemm config: R6 tiling, doubled k-split for grid occupancy ---- */
#define GTM 32           /* m per CTA = full b */
#define GKSPLIT 100
#define GVT 80           /* v per CTA */
#define GKC 16           /* v sub-chunk */
#define GNCH (GVT/GKC)   /* 5 */
#define ASTR 36          /* padded As row stride (floats), 16B-aligned */

// ---------------- scratch (device globals, no allocations) ----------------
__device__ float g_cn[BB*DD];
__device__ float g_cos[BB*VV];
__device__ float g_Abar[(size_t)BB*SS*VV];    // [B*S, V] (8 MB)

__device__ __forceinline__ float warpReduceSum(float v){
    #pragma unroll
    for (int o = 16; o > 0; o >>= 1) v += __shfl_down_sync(0xffffffffu, v, o);
    return v;
}
__device__ __forceinline__ unsigned long long splat2(float f){
    unsigned long long r; asm("mov.b64 %0, {%1,%1};" : "=l"(r) : "f"(f)); return r;
}
__device__ __forceinline__ void fma2(unsigned long long& a, unsigned long long x, unsigned long long y){
    asm("fma.rn.f32x2 %0, %1, %2, %0;" : "+l"(a) : "l"(x), "l"(y));
}

// ---------------- kernel 1: context + normalize (parallel over s) ----------------
__global__ void __launch_bounds__(1024)
ctx_kernel(const int* __restrict__ concepts,
           const int* __restrict__ clen,
           const int* __restrict__ segl,
           const float* __restrict__ embedw){
    __shared__ float sm[8*DD];
    __shared__ float redn[32];
    int b = blockIdx.x;
    int g = threadIdx.x >> 7;
    int d = threadIdx.x & 127;
    int seg = segl[b];

    float part = 0.f;
    for (int s = g; s < seg; s += 8){
        int bs = b*SS + s;
        int len = clen[bs];
        if (len > 0){
            const int4* ci = (const int4*)(concepts + bs*PP);
            int4 c0 = ci[0], c1 = ci[1];
            float sum = 0.f;
            if (0 < len) sum += __ldg(&embedw[(size_t)c0.x*DD + d]);
            if (1 < len) sum += __ldg(&embedw[(size_t)c0.y*DD + d]);
            if (2 < len) sum += __ldg(&embedw[(size_t)c0.z*DD + d]);
            if (3 < len) sum += __ldg(&embedw[(size_t)c0.w*DD + d]);
            if (4 < len) sum += __ldg(&embedw[(size_t)c1.x*DD + d]);
            if (5 < len) sum += __ldg(&embedw[(size_t)c1.y*DD + d]);
            if (6 < len) sum += __ldg(&embedw[(size_t)c1.z*DD + d]);
            if (7 < len) sum += __ldg(&embedw[(size_t)c1.w*DD + d]);
            part += sum / (float)len;
        }
    }
    sm[g*DD + d] = part;
    __syncthreads();

    float ctx = 0.f;
    #pragma unroll
    for (int k = 0; k < 8; ++k) ctx += sm[k*DD + d];
    ctx /= (float)seg;

    int warp = threadIdx.x >> 5, lane = threadIdx.x & 31;
    float sq = warpReduceSum(ctx*ctx);
    if (lane == 0) redn[warp] = sq;
    __syncthreads();
    float n2 = redn[0] + redn[1] + redn[2] + redn[3];
    if (g == 0) g_cn[b*DD + d] = ctx / fmaxf(sqrtf(n2), EPSF);
}

// ---------------- kernel 2: abs cosine sim + fused output zeroing ----------------
__global__ void cos_kernel(const float* __restrict__ kb, float* __restrict__ out){
    if (blockIdx.x < (BB*SS*DD)/256)
        out[blockIdx.x*256 + threadIdx.x] = 0.f;

    int warp = threadIdx.x >> 5, lane = threadIdx.x & 31;
    int v = blockIdx.x*8 + warp;
    if (v >= VV) return;
    const float4* row4 = (const float4*)(kb + (size_t)v*DD);
    float4 kv = row4[lane];
    float nr = kv.x*kv.x + kv.y*kv.y + kv.z*kv.z + kv.w*kv.w;
    nr = warpReduceSum(nr);
    nr = __shfl_sync(0xffffffffu, nr, 0);
    float inv = 1.0f / fmaxf(sqrtf(nr), EPSF);
    #pragma unroll
    for (int b = 0; b < BB; ++b){
        const float4* cn4 = (const float4*)(g_cn + b*DD);
        float4 c = cn4[lane];
        float dt = kv.x*c.x + kv.y*c.y + kv.z*c.z + kv.w*c.w;
        dt = warpReduceSum(dt);
        if (lane == 0) g_cos[(size_t)b*VV + v] = fabsf(dt)*inv;
    }
}

// ---------------- kernel 3: register-resident fused attention ----------------
// 2 barriers per p: parity ping-ponged disjoint reduce buffers (redA minmax, redB sum).
__global__ void __launch_bounds__(NT_ATTN, 1)
attn_kernel(const int* __restrict__ concepts,
            const int* __restrict__ clen,
            const int* __restrict__ segl,
            const float* __restrict__ edge,
            const float* __restrict__ aff,
            const float* __restrict__ lam){
    __shared__ float redA[2][32];
    __shared__ float redB[2][16];
    int bs = blockIdx.x;
    int b = bs >> 5, s = bs & 31;
    int tid = threadIdx.x;
    int warp = tid >> 5, lane = tid & 31;

    float4 racc[4];
    #pragma unroll
    for (int k = 0; k < 4; ++k) racc[k] = make_float4(0.f, 0.f, 0.f, 0.f);

    int seg = segl[b];
    int len = (s < seg) ? clen[bs] : 0;

    if (len > 0){
        float invden = 1.0f / (float)len;
        const float4* cos4 = (const float4*)(g_cos + (size_t)b*VV);
        const float4* lam4 = (const float4*)lam;
        const float4* aff4 = (const float4*)aff;
        const int*    cp   = concepts + bs*PP;

        float4 A[4], Bv[4];
        #pragma unroll
        for (int k = 0; k < 4; ++k){
            int i = tid + k*NT_ATTN;
            if (i < NQ){
                float4 l  = lam4[i];
                float4 cf = cos4[i];
                float4 af = aff4[i];
                A[k].x = CONCF*l.x*cf.x; A[k].y = CONCF*l.y*cf.y;
                A[k].z = CONCF*l.z*cf.z; A[k].w = CONCF*l.w*cf.w;
                Bv[k].x = CONCF*(1.f-l.x)*af.x; Bv[k].y = CONCF*(1.f-l.y)*af.y;
                Bv[k].z = CONCF*(1.f-l.z)*af.z; Bv[k].w = CONCF*(1.f-l.w)*af.w;
            }
        }

        float4 E[4], F[4];
        {
            int c = __ldg(&cp[0]);
            const float4* r = (const float4*)(edge + (size_t)c*VV);
            #pragma unroll
            for (int k = 0; k < 4; ++k){
                int i = tid + k*NT_ATTN;
                if (i < NQ) E[k] = __ldcs(&r[i]);
            }
        }

        for (int p = 0; p < len; ++p){
            int q = p & 1;
            if (p + 1 < len){
                int c = __ldg(&cp[p+1]);
                const float4* r = (const float4*)(edge + (size_t)c*VV);
                #pragma unroll
                for (int k = 0; k < 4; ++k){
                    int i = tid + k*NT_ATTN;
                    if (i < NQ) F[k] = __ldcs(&r[i]);
                }
            }

            float mx = -1e30f, mn = 1e30f;
            #pragma unroll
            for (int k = 0; k < 4; ++k){
                int i = tid + k*NT_ATTN;
                if (i < NQ){
                    mx = fmaxf(mx, fmaxf(fmaxf(E[k].x, E[k].y), fmaxf(E[k].z, E[k].w)));
                    mn = fminf(mn, fminf(fminf(E[k].x, E[k].y), fminf(E[k].z, E[k].w)));
                }
            }
            #pragma unroll
            for (int o = 16; o > 0; o >>= 1){
                mx = fmaxf(mx, __shfl_down_sync(0xffffffffu, mx, o));
                mn = fminf(mn, __shfl_down_sync(0xffffffffu, mn, o));
            }
            if (lane == 0){ redA[q][warp] = mx; redA[q][16 + warp] = mn; }
            __syncthreads();
            float rmx = -1e30f, rmn = 1e30f;
            #pragma unroll
            for (int i = 0; i < 16; ++i){
                rmx = fmaxf(rmx, redA[q][i]);
                rmn = fminf(rmn, redA[q][16 + i]);
            }
            float rng  = rmx - rmn;
            float invr = 1.0f / (rng + ((rng == 0.0f) ? 1.0f : 0.0f));

            float ss = 0.f;
            #pragma unroll
            for (int k = 0; k < 4; ++k){
                int i = tid + k*NT_ATTN;
                if (i < NQ){
                    float4 ex;
                    ex.x = __expf((E[k].x*invr)*A[k].x + ((E[k].x > 0.f) ? Bv[k].x : 0.f));
                    ex.y = __expf((E[k].y*invr)*A[k].y + ((E[k].y > 0.f) ? Bv[k].y : 0.f));
                    ex.z = __expf((E[k].z*invr)*A[k].z + ((E[k].z > 0.f) ? Bv[k].z : 0.f));
                    ex.w = __expf((E[k].w*invr)*A[k].w + ((E[k].w > 0.f) ? Bv[k].w : 0.f));
                    E[k] = ex;
                    ss += (ex.x + ex.y) + (ex.z + ex.w);
                }
            }
            ss = warpReduceSum(ss);
            if (lane == 0) redB[q][warp] = ss;
            __syncthreads();
            float tot = 0.f;
            #pragma unroll
            for (int i = 0; i < 16; ++i) tot += redB[q][i];
            float scale = invden / tot;

            #pragma unroll
            for (int k = 0; k < 4; ++k){
                int i = tid + k*NT_ATTN;
                if (i < NQ){
                    racc[k].x += E[k].x*scale;
                    racc[k].y += E[k].y*scale;
                    racc[k].z += E[k].z*scale;
                    racc[k].w += E[k].w*scale;
                }
            }
            #pragma unroll
            for (int k = 0; k < 4; ++k) E[k] = F[k];
        }
    }

    float4* ob = (float4*)(g_Abar + (size_t)bs*VV);
    #pragma unroll
    for (int k = 0; k < 4; ++k){
        int i = tid + k*NT_ATTN;
        if (i < NQ) ob[i] = racc[k];
    }
}

// ---------------- kernel 4: register-tiled GEMM out[256,128] = Abar @ kb ----------------
// R6 mapping (4m x 4d per thread), grid doubled via GKSPLIT=100 for occupancy.
__global__ void __launch_bounds__(256, 4)
gemm_kernel(const float* __restrict__ kb,
            const int* __restrict__ segl,
            float* __restrict__ out){
    __shared__ __align__(16) float As[2][GKC*ASTR];   // [v][m] padded, 2.3 KB x2
    __shared__ __align__(16) float Bs[2][GKC*DD];     // [v][d], 8 KB x2
    int mt = blockIdx.x;             // == b
    int ks = blockIdx.y;
    int m0 = mt*GTM;
    int seg = segl[mt];
    int tid = threadIdx.x;
    int mg  = tid >> 5;              // warp id -> m group
    int dg  = tid & 31;              // lane    -> d group
    int v0  = ks*GVT;
    bool active = (mg*4 < seg);      // whole-warp skip for masked s rows

    // loader roles
    int am  = tid >> 2, avq = tid & 3;                 // As: threads 0..127
    const float* aptr = &g_Abar[(size_t)(m0 + am)*VV + v0];
    int bdq = tid & 31;                                // Bs: all 256, 2 float4 each
    int bv0 = tid >> 5, bv1 = (tid + 256) >> 5;
    const float* bptr = &kb[(size_t)v0*DD];

    float4 rA, rB0, rB1;
    // ldg chunk 0
    if (tid < 128) rA = *(const float4*)(aptr + avq*4);
    rB0 = *(const float4*)(bptr + (size_t)bv0*DD + bdq*4);
    rB1 = *(const float4*)(bptr + (size_t)bv1*DD + bdq*4);
    // sts chunk 0
    if (tid < 128){
        As[0][(avq*4 + 0)*ASTR + am] = rA.x;
        As[0][(avq*4 + 1)*ASTR + am] = rA.y;
        As[0][(avq*4 + 2)*ASTR + am] = rA.z;
        As[0][(avq*4 + 3)*ASTR + am] = rA.w;
    }
    *(float4*)(&Bs[0][bv0*DD + bdq*4]) = rB0;
    *(float4*)(&Bs[0][bv1*DD + bdq*4]) = rB1;
    __syncthreads();

    unsigned long long acc[8];
    #pragma unroll
    for (int i = 0; i < 8; ++i) acc[i] = 0ULL;

    for (int c = 0; c < GNCH; ++c){
        if (c + 1 < GNCH){
            int vc = (c + 1)*GKC;
            if (tid < 128) rA = *(const float4*)(aptr + vc + avq*4);
            rB0 = *(const float4*)(bptr + (size_t)(vc + bv0)*DD + bdq*4);
            rB1 = *(const float4*)(bptr + (size_t)(vc + bv1)*DD + bdq*4);
        }
        if (active){
            const float* AsB = As[c & 1];
            const float* BsB = Bs[c & 1];
            #pragma unroll
            for (int v = 0; v < GKC; ++v){
                double2 av = *(const double2*)(AsB + v*ASTR + mg*4);   // (a0,a1),(a2,a3) broadcast
                float4  bv = *(const float4*) (BsB + v*DD  + dg*4);
                unsigned long long a01 = __double_as_longlong(av.x);
                unsigned long long a23 = __double_as_longlong(av.y);
                unsigned long long b0 = splat2(bv.x);
                unsigned long long b1 = splat2(bv.y);
                unsigned long long b2 = splat2(bv.z);
                unsigned long long b3 = splat2(bv.w);
                fma2(acc[0], a01, b0); fma2(acc[1], a01, b1);
                fma2(acc[2], a01, b2); fma2(acc[3], a01, b3);
                fma2(acc[4], a23, b0); fma2(acc[5], a23, b1);
                fma2(acc[6], a23, b2); fma2(acc[7], a23, b3);
            }
        }
        if (c + 1 < GNCH){
            int bb = (c + 1) & 1;
            if (tid < 128){
                As[bb][(avq*4 + 0)*ASTR + am] = rA.x;
                As[bb][(avq*4 + 1)*ASTR + am] = rA.y;
                As[bb][(avq*4 + 2)*ASTR + am] = rA.z;
                As[bb][(avq*4 + 3)*ASTR + am] = rA.w;
            }
            *(float4*)(&Bs[bb][bv0*DD + bdq*4]) = rB0;
            *(float4*)(&Bs[bb][bv1*DD + bdq*4]) = rB1;
        }
        __syncthreads();
    }

    if (active){
        int mbase = m0 + mg*4;
        int dbase = dg*4;
        #pragma unroll
        for (int mp = 0; mp < 2; ++mp){
            #pragma unroll
            for (int dj = 0; dj < 4; ++dj){
                float lo, hi;
                asm("mov.b64 {%0,%1}, %2;" : "=f"(lo), "=f"(hi) : "l"(acc[mp*4 + dj]));
                atomicAdd(&out[(size_t)(mbase + 2*mp    )*DD + dbase + dj], lo);
                atomicAdd(&out[(size_t)(mbase + 2*mp + 1)*DD + dbase + dj], hi);
            }
        }
    }
}

// ---------------- launch ----------------
extern "C" void kernel_launch(void* const* d_in, const int* in_sizes, int n_in,
                              void* d_out, int out_size){
    (void)in_sizes; (void)n_in; (void)out_size;
    const int*   concepts = (const int*)  d_in[0];
    const int*   clen     = (const int*)  d_in[1];
    const int*   segl     = (const int*)  d_in[2];
    const float* embedw   = (const float*)d_in[3];
    const float* kb       = (const float*)d_in[4];
    const float* edge     = (const float*)d_in[5];
    const float* aff      = (const float*)d_in[6];
    const float* lam      = (const float*)d_in[7];
    float* out = (float*)d_out;

    ctx_kernel <<<BB, 1024>>>(concepts, clen, segl, embedw);
    cos_kernel <<<VV/8, 256>>>(kb, out);
    attn_kernel<<<BB*SS, NT_ATTN>>>(concepts, clen, segl, edge, aff, lam);
    gemm_kernel<<<dim3(BB, GKSPLIT), 256>>>(kb, segl, out);
}

// round 11
// speedup vs baseline: 1.1382x; 1.1382x over previous
#include <cuda_runtime.h>

#define BB 8
#define SS 32
#define PP 8
#define VV 8000
#define DD 128
#define CONCF 5.0f
#define EPSF 1e-8f

#define NT_ATTN 512
#define NQ (VV/4)        /* 2000 float4 per row */

/* ---- gemm config: R9 split, bigger chunks + cp.async ---- */
#define GTM 32           /* m per CTA = full b */
#define GKSPLIT 50
#define GVT 160          /* v per CTA */
#define GKC 32           /* v per staged chunk */
#define GNCH (GVT/GKC)   /* 5 */
#define ASTR 36          /* padded As row stride (floats), 16B-aligned */

// ---------------- scratch (device globals, no allocations) ----------------
__device__ float g_cn[BB*DD];
__device__ float g_cos[BB*VV];
__device__ float g_Abar[(size_t)BB*SS*VV];    // [B*S, V] (8 MB)

__device__ __forceinline__ float warpReduceSum(float v){
    #pragma unroll
    for (int o = 16; o > 0; o >>= 1) v += __shfl_down_sync(0xffffffffu, v, o);
    return v;
}
__device__ __forceinline__ unsigned long long splat2(float f){
    unsigned long long r; asm("mov.b64 %0, {%1,%1};" : "=l"(r) : "f"(f)); return r;
}
__device__ __forceinline__ void fma2(unsigned long long& a, unsigned long long x, unsigned long long y){
    asm("fma.rn.f32x2 %0, %1, %2, %0;" : "+l"(a) : "l"(x), "l"(y));
}
__device__ __forceinline__ void cpasync16(unsigned s, const void* g){
    asm volatile("cp.async.ca.shared.global [%0], [%1], 16;" :: "r"(s), "l"(g));
}

// ---------------- kernel 1: context + normalize (parallel over s) ----------------
__global__ void __launch_bounds__(1024)
ctx_kernel(const int* __restrict__ concepts,
           const int* __restrict__ clen,
           const int* __restrict__ segl,
           const float* __restrict__ embedw){
    __shared__ float sm[8*DD];
    __shared__ float redn[32];
    int b = blockIdx.x;
    int g = threadIdx.x >> 7;
    int d = threadIdx.x & 127;
    int seg = segl[b];

    float part = 0.f;
    for (int s = g; s < seg; s += 8){
        int bs = b*SS + s;
        int len = clen[bs];
        if (len > 0){
            const int4* ci = (const int4*)(concepts + bs*PP);
            int4 c0 = ci[0], c1 = ci[1];
            float sum = 0.f;
            if (0 < len) sum += __ldg(&embedw[(size_t)c0.x*DD + d]);
            if (1 < len) sum += __ldg(&embedw[(size_t)c0.y*DD + d]);
            if (2 < len) sum += __ldg(&embedw[(size_t)c0.z*DD + d]);
            if (3 < len) sum += __ldg(&embedw[(size_t)c0.w*DD + d]);
            if (4 < len) sum += __ldg(&embedw[(size_t)c1.x*DD + d]);
            if (5 < len) sum += __ldg(&embedw[(size_t)c1.y*DD + d]);
            if (6 < len) sum += __ldg(&embedw[(size_t)c1.z*DD + d]);
            if (7 < len) sum += __ldg(&embedw[(size_t)c1.w*DD + d]);
            part += sum / (float)len;
        }
    }
    sm[g*DD + d] = part;
    __syncthreads();

    float ctx = 0.f;
    #pragma unroll
    for (int k = 0; k < 8; ++k) ctx += sm[k*DD + d];
    ctx /= (float)seg;

    int warp = threadIdx.x >> 5, lane = threadIdx.x & 31;
    float sq = warpReduceSum(ctx*ctx);
    if (lane == 0) redn[warp] = sq;
    __syncthreads();
    float n2 = redn[0] + redn[1] + redn[2] + redn[3];
    if (g == 0) g_cn[b*DD + d] = ctx / fmaxf(sqrtf(n2), EPSF);
}

// ---------------- kernel 2: abs cosine sim + fused output zeroing ----------------
__global__ void cos_kernel(const float* __restrict__ kb, float* __restrict__ out){
    if (blockIdx.x < (BB*SS*DD)/256)
        out[blockIdx.x*256 + threadIdx.x] = 0.f;

    int warp = threadIdx.x >> 5, lane = threadIdx.x & 31;
    int v = blockIdx.x*8 + warp;
    if (v >= VV) return;
    const float4* row4 = (const float4*)(kb + (size_t)v*DD);
    float4 kv = row4[lane];
    float nr = kv.x*kv.x + kv.y*kv.y + kv.z*kv.z + kv.w*kv.w;
    nr = warpReduceSum(nr);
    nr = __shfl_sync(0xffffffffu, nr, 0);
    float inv = 1.0f / fmaxf(sqrtf(nr), EPSF);
    #pragma unroll
    for (int b = 0; b < BB; ++b){
        const float4* cn4 = (const float4*)(g_cn + b*DD);
        float4 c = cn4[lane];
        float dt = kv.x*c.x + kv.y*c.y + kv.z*c.z + kv.w*c.w;
        dt = warpReduceSum(dt);
        if (lane == 0) g_cos[(size_t)b*VV + v] = fabsf(dt)*inv;
    }
}

// ---------------- kernel 3: register-resident fused attention ----------------
// 2 barriers per p: parity ping-ponged disjoint reduce buffers (redA minmax, redB sum).
__global__ void __launch_bounds__(NT_ATTN, 1)
attn_kernel(const int* __restrict__ concepts,
            const int* __restrict__ clen,
            const int* __restrict__ segl,
            const float* __restrict__ edge,
            const float* __restrict__ aff,
            const float* __restrict__ lam){
    __shared__ float redA[2][32];
    __shared__ float redB[2][16];
    int bs = blockIdx.x;
    int b = bs >> 5, s = bs & 31;
    int tid = threadIdx.x;
    int warp = tid >> 5, lane = tid & 31;

    float4 racc[4];
    #pragma unroll
    for (int k = 0; k < 4; ++k) racc[k] = make_float4(0.f, 0.f, 0.f, 0.f);

    int seg = segl[b];
    int len = (s < seg) ? clen[bs] : 0;

    if (len > 0){
        float invden = 1.0f / (float)len;
        const float4* cos4 = (const float4*)(g_cos + (size_t)b*VV);
        const float4* lam4 = (const float4*)lam;
        const float4* aff4 = (const float4*)aff;
        const int*    cp   = concepts + bs*PP;

        float4 A[4], Bv[4];
        #pragma unroll
        for (int k = 0; k < 4; ++k){
            int i = tid + k*NT_ATTN;
            if (i < NQ){
                float4 l  = lam4[i];
                float4 cf = cos4[i];
                float4 af = aff4[i];
                A[k].x = CONCF*l.x*cf.x; A[k].y = CONCF*l.y*cf.y;
                A[k].z = CONCF*l.z*cf.z; A[k].w = CONCF*l.w*cf.w;
                Bv[k].x = CONCF*(1.f-l.x)*af.x; Bv[k].y = CONCF*(1.f-l.y)*af.y;
                Bv[k].z = CONCF*(1.f-l.z)*af.z; Bv[k].w = CONCF*(1.f-l.w)*af.w;
            }
        }

        float4 E[4], F[4];
        {
            int c = __ldg(&cp[0]);
            const float4* r = (const float4*)(edge + (size_t)c*VV);
            #pragma unroll
            for (int k = 0; k < 4; ++k){
                int i = tid + k*NT_ATTN;
                if (i < NQ) E[k] = __ldcs(&r[i]);
            }
        }

        for (int p = 0; p < len; ++p){
            int q = p & 1;
            if (p + 1 < len){
                int c = __ldg(&cp[p+1]);
                const float4* r = (const float4*)(edge + (size_t)c*VV);
                #pragma unroll
                for (int k = 0; k < 4; ++k){
                    int i = tid + k*NT_ATTN;
                    if (i < NQ) F[k] = __ldcs(&r[i]);
                }
            }

            float mx = -1e30f, mn = 1e30f;
            #pragma unroll
            for (int k = 0; k < 4; ++k){
                int i = tid + k*NT_ATTN;
                if (i < NQ){
                    mx = fmaxf(mx, fmaxf(fmaxf(E[k].x, E[k].y), fmaxf(E[k].z, E[k].w)));
                    mn = fminf(mn, fminf(fminf(E[k].x, E[k].y), fminf(E[k].z, E[k].w)));
                }
            }
            #pragma unroll
            for (int o = 16; o > 0; o >>= 1){
                mx = fmaxf(mx, __shfl_down_sync(0xffffffffu, mx, o));
                mn = fminf(mn, __shfl_down_sync(0xffffffffu, mn, o));
            }
            if (lane == 0){ redA[q][warp] = mx; redA[q][16 + warp] = mn; }
            __syncthreads();
            float rmx = -1e30f, rmn = 1e30f;
            #pragma unroll
            for (int i = 0; i < 16; ++i){
                rmx = fmaxf(rmx, redA[q][i]);
                rmn = fminf(rmn, redA[q][16 + i]);
            }
            float rng  = rmx - rmn;
            float invr = 1.0f / (rng + ((rng == 0.0f) ? 1.0f : 0.0f));

            float ss = 0.f;
            #pragma unroll
            for (int k = 0; k < 4; ++k){
                int i = tid + k*NT_ATTN;
                if (i < NQ){
                    float4 ex;
                    ex.x = __expf((E[k].x*invr)*A[k].x + ((E[k].x > 0.f) ? Bv[k].x : 0.f));
                    ex.y = __expf((E[k].y*invr)*A[k].y + ((E[k].y > 0.f) ? Bv[k].y : 0.f));
                    ex.z = __expf((E[k].z*invr)*A[k].z + ((E[k].z > 0.f) ? Bv[k].z : 0.f));
                    ex.w = __expf((E[k].w*invr)*A[k].w + ((E[k].w > 0.f) ? Bv[k].w : 0.f));
                    E[k] = ex;
                    ss += (ex.x + ex.y) + (ex.z + ex.w);
                }
            }
            ss = warpReduceSum(ss);
            if (lane == 0) redB[q][warp] = ss;
            __syncthreads();
            float tot = 0.f;
            #pragma unroll
            for (int i = 0; i < 16; ++i) tot += redB[q][i];
            float scale = invden / tot;

            #pragma unroll
            for (int k = 0; k < 4; ++k){
                int i = tid + k*NT_ATTN;
                if (i < NQ){
                    racc[k].x += E[k].x*scale;
                    racc[k].y += E[k].y*scale;
                    racc[k].z += E[k].z*scale;
                    racc[k].w += E[k].w*scale;
                }
            }
            #pragma unroll
            for (int k = 0; k < 4; ++k) E[k] = F[k];
        }
    }

    float4* ob = (float4*)(g_Abar + (size_t)bs*VV);
    #pragma unroll
    for (int k = 0; k < 4; ++k){
        int i = tid + k*NT_ATTN;
        if (i < NQ) ob[i] = racc[k];
    }
}

// ---------------- kernel 4: GEMM out[256,128] = Abar @ kb ----------------
// R6/R9 4m x 4d thread mapping; B tile staged via cp.async (no reg staging,
// latency off the scoreboard); GKC=32 halves barrier count; masked A rows
// zero-filled in smem instead of loaded.
__global__ void __launch_bounds__(256, 4)
gemm_kernel(const float* __restrict__ kb,
            const int* __restrict__ segl,
            float* __restrict__ out){
    __shared__ __align__(16) float As[2][GKC*ASTR];   // [v][m] padded, 4.6 KB x2
    __shared__ __align__(16) float Bs[2][GKC*DD];     // [v][d], 16 KB x2
    int mt = blockIdx.x;             // == b
    int ks = blockIdx.y;
    int m0 = mt*GTM;
    int seg = segl[mt];
    int tid = threadIdx.x;
    int mg  = tid >> 5;              // warp id -> m group
    int dg  = tid & 31;              // lane    -> d group
    int v0  = ks*GVT;
    bool active = (mg*4 < seg);      // whole-warp skip for masked s rows

    // A loader: 256 threads, am = m row (0..31), avq = float4 index (0..7 = 32 v)
    int am = tid >> 3, avq = tid & 7;
    bool arow = (am < seg);                            // masked rows -> zeros
    const float* aptr = &g_Abar[(size_t)(m0 + am)*VV + v0 + avq*4];
    const float* bptr = &kb[(size_t)v0*DD];

    unsigned bs_base0 = (unsigned)__cvta_generic_to_shared(&Bs[0][0]);
    unsigned bs_base1 = (unsigned)__cvta_generic_to_shared(&Bs[1][0]);

    // ---- prologue: chunk 0 ----
    {
        #pragma unroll
        for (int j = 0; j < 4; ++j){
            int idx = tid + j*256, bv = idx >> 5, bd = idx & 31;
            cpasync16(bs_base0 + (unsigned)((bv*DD + bd*4)*4),
                      bptr + (size_t)bv*DD + bd*4);
        }
        asm volatile("cp.async.commit_group;");
        float4 rA = arow ? __ldcs((const float4*)aptr)
                         : make_float4(0.f, 0.f, 0.f, 0.f);
        As[0][(avq*4 + 0)*ASTR + am] = rA.x;
        As[0][(avq*4 + 1)*ASTR + am] = rA.y;
        As[0][(avq*4 + 2)*ASTR + am] = rA.z;
        As[0][(avq*4 + 3)*ASTR + am] = rA.w;
        asm volatile("cp.async.wait_group 0;");
    }
    __syncthreads();

    unsigned long long acc[8];
    #pragma unroll
    for (int i = 0; i < 8; ++i) acc[i] = 0ULL;

    for (int c = 0; c < GNCH; ++c){
        float4 rA;
        if (c + 1 < GNCH){
            int vc = (c + 1)*GKC;
            unsigned bsb = ((c + 1) & 1) ? bs_base1 : bs_base0;
            #pragma unroll
            for (int j = 0; j < 4; ++j){
                int idx = tid + j*256, bv = idx >> 5, bd = idx & 31;
                cpasync16(bsb + (unsigned)((bv*DD + bd*4)*4),
                          bptr + (size_t)(vc + bv)*DD + bd*4);
            }
            asm volatile("cp.async.commit_group;");
            rA = arow ? __ldcs((const float4*)(aptr + vc))
                      : make_float4(0.f, 0.f, 0.f, 0.f);
        }
        if (active){
            const float* AsB = As[c & 1];
            const float* BsB = Bs[c & 1];
            #pragma unroll
            for (int v = 0; v < GKC; ++v){
                double2 av = *(const double2*)(AsB + v*ASTR + mg*4);   // (a0,a1),(a2,a3) broadcast
                float4  bv = *(const float4*) (BsB + v*DD  + dg*4);
                unsigned long long a01 = __double_as_longlong(av.x);
                unsigned long long a23 = __double_as_longlong(av.y);
                unsigned long long b0 = splat2(bv.x);
                unsigned long long b1 = splat2(bv.y);
                unsigned long long b2 = splat2(bv.z);
                unsigned long long b3 = splat2(bv.w);
                fma2(acc[0], a01, b0); fma2(acc[1], a01, b1);
                fma2(acc[2], a01, b2); fma2(acc[3], a01, b3);
                fma2(acc[4], a23, b0); fma2(acc[5], a23, b1);
                fma2(acc[6], a23, b2); fma2(acc[7], a23, b3);
            }
        }
        if (c + 1 < GNCH){
            int bb = (c + 1) & 1;
            As[bb][(avq*4 + 0)*ASTR + am] = rA.x;
            As[bb][(avq*4 + 1)*ASTR + am] = rA.y;
            As[bb][(avq*4 + 2)*ASTR + am] = rA.z;
            As[bb][(avq*4 + 3)*ASTR + am] = rA.w;
            asm volatile("cp.async.wait_group 0;");
        }
        __syncthreads();
    }

    if (active){
        int mbase = m0 + mg*4;
        int dbase = dg*4;
        #pragma unroll
        for (int mp = 0; mp < 2; ++mp){
            #pragma unroll
            for (int dj = 0; dj < 4; ++dj){
                float lo, hi;
                asm("mov.b64 {%0,%1}, %2;" : "=f"(lo), "=f"(hi) : "l"(acc[mp*4 + dj]));
                atomicAdd(&out[(size_t)(mbase + 2*mp    )*DD + dbase + dj], lo);
                atomicAdd(&out[(size_t)(mbase + 2*mp + 1)*DD + dbase + dj], hi);
            }
        }
    }
}

// ---------------- launch ----------------
extern "C" void kernel_launch(void* const* d_in, const int* in_sizes, int n_in,
                              void* d_out, int out_size){
    (void)in_sizes; (void)n_in; (void)out_size;
    const int*   concepts = (const int*)  d_in[0];
    const int*   clen     = (const int*)  d_in[1];
    const int*   segl     = (const int*)  d_in[2];
    const float* embedw   = (const float*)d_in[3];
    const float* kb       = (const float*)d_in[4];
    const float* edge     = (const float*)d_in[5];
    const float* aff      = (const float*)d_in[6];
    const float* lam      = (const float*)d_in[7];
    float* out = (float*)d_out;

    ctx_kernel <<<BB, 1024>>>(concepts, clen, segl, embedw);
    cos_kernel <<<VV/8, 256>>>(kb, out);
    attn_kernel<<<BB*SS, NT_ATTN>>>(concepts, clen, segl, edge, aff, lam);
    gemm_kernel<<<dim3(BB, GKSPLIT), 256>>>(kb, segl, out);
}